// round 5
// baseline (speedup 1.0000x reference)
#include <cuda_runtime.h>
#include <cuda_bf16.h>
#include <cstdint>
#include <math.h>

#define BDIM 64
#define SDIM 2048
#define HDIM 1024
#define KDIM 2048   // 2H contraction
#define NDIM 1024   // H energy dim

#define TM 64
#define TN 64
#define TK 16

// scratch (allocation-free rule: __device__ globals)
__device__ float g_hWh[BDIM * NDIM];              // hidden@Wh + b_attn
__device__ float g_part[16 * BDIM * SDIM];        // per-nTile partial scores (16 n-tiles)

// ------------------------------------------------- kernel 1: hWh + b_attn
// one thread per (b, n); plain global reads (W coalesced, hidden broadcast)
__global__ void hwh_kernel(const float* __restrict__ hidden,
                           const float* __restrict__ W,
                           const float* __restrict__ b_attn) {
  const int n = blockIdx.x * 256 + threadIdx.x;   // grid.x = 4 -> n in [0,1024)
  const int b = blockIdx.y;                       // grid.y = 64
  float acc = b_attn[n];
  const float* hrow = hidden + (long long)b * HDIM;
  for (int h = 0; h < HDIM; h++)
    acc = fmaf(hrow[h], W[(long long)h * NDIM + n], acc);   // Wh = W_attn[:H]
  g_hWh[(long long)b * NDIM + n] = acc;
}

// ------------- kernel 2: E = enc@We tile ; partial = sum_n v*tanh(E+hWh)
// plain scalar smem-tiled fp32 GEMM, 64x64x16 tiles, 4x4 per thread.
__global__ __launch_bounds__(256)
void energy_simple_kernel(const float* __restrict__ enc,
                          const float* __restrict__ W,
                          const float* __restrict__ v) {
  __shared__ __align__(16) float As[TM][TK + 1];   // 64 x 17
  __shared__ __align__(16) float Bs[TK][TN + 1];   // 16 x 65
  __shared__ __align__(16) float s_hwh[TN];
  __shared__ __align__(16) float s_v[TN];
  __shared__ __align__(16) float E[TM][16];        // per-(row, txgroup) partials

  const int tid = threadIdx.x;     // 256
  const int tx  = tid & 15;        // 0..15 (col group)
  const int ty  = tid >> 4;        // 0..15 (row group)

  const int nt = blockIdx.x;                   // 0..15
  const int mt = blockIdx.y;                   // 0..2047
  const int n0 = nt * TN;
  const long long row0 = (long long)mt * TM;   // global m base (over B*S)
  const int bidx = mt >> 5;                    // 32 m-tiles per batch (S/TM)

  const float* A  = enc + row0 * KDIM;
  const float* Bw = W + (long long)HDIM * NDIM + n0;   // We = W_attn[H:]

  float c[4][4];
  #pragma unroll
  for (int i = 0; i < 4; i++)
    #pragma unroll
    for (int j = 0; j < 4; j++) c[i][j] = 0.0f;

  for (int k0 = 0; k0 < KDIM; k0 += TK) {
    // stage A tile 64x16 (1024 elems / 256 threads = 4 each)
    #pragma unroll
    for (int i = tid; i < TM * TK; i += 256) {
      const int r = i >> 4, cc = i & 15;
      As[r][cc] = A[(long long)r * KDIM + k0 + cc];
    }
    // stage B tile 16x64
    #pragma unroll
    for (int i = tid; i < TK * TN; i += 256) {
      const int r = i >> 6, cc = i & 63;
      Bs[r][cc] = Bw[(long long)(k0 + r) * NDIM + cc];
    }
    __syncthreads();

    #pragma unroll
    for (int k = 0; k < TK; k++) {
      float av[4], bv[4];
      #pragma unroll
      for (int i = 0; i < 4; i++) av[i] = As[ty * 4 + i][k];
      #pragma unroll
      for (int j = 0; j < 4; j++) bv[j] = Bs[k][tx * 4 + j];
      #pragma unroll
      for (int i = 0; i < 4; i++)
        #pragma unroll
        for (int j = 0; j < 4; j++)
          c[i][j] = fmaf(av[i], bv[j], c[i][j]);
    }
    __syncthreads();
  }

  // epilogue: + hWh, tanh, dot v over this 64-col slice
  if (tid < TN) {
    s_hwh[tid] = g_hWh[(long long)bidx * NDIM + n0 + tid];
    s_v[tid]   = v[n0 + tid];
  }
  __syncthreads();

  #pragma unroll
  for (int i = 0; i < 4; i++) {
    float pr = 0.0f;
    #pragma unroll
    for (int j = 0; j < 4; j++) {
      const int nl = tx * 4 + j;
      pr += tanhf(c[i][j] + s_hwh[nl]) * s_v[nl];
    }
    E[ty * 4 + i][tx] = pr;
  }
  __syncthreads();

  if (tid < TM) {
    float s = 0.0f;
    #pragma unroll
    for (int j = 0; j < 16; j++) s += E[tid][j];
    g_part[(long long)nt * (BDIM * SDIM) + row0 + tid] = s;
  }
}

// ------------------------------------------ kernel 3: mask + softmax(S)
__global__ void softmax_kernel(const int* __restrict__ mask,
                               float* __restrict__ out) {
  const int bq = blockIdx.x;     // 0..63
  const int tid = threadIdx.x;   // 256
  float loc[8];
  float mx = -1e30f;
  #pragma unroll
  for (int i = 0; i < 8; i++) {
    const long long idx = (long long)bq * SDIM + i * 256 + tid;
    float sc = 0.0f;
    #pragma unroll
    for (int j = 0; j < 16; j++) sc += g_part[(long long)j * (BDIM * SDIM) + idx];
    if (mask[idx] == 0) sc = -1e9f;
    loc[i] = sc;
    mx = fmaxf(mx, sc);
  }
  __shared__ float sm[8];
  #pragma unroll
  for (int o = 16; o > 0; o >>= 1) mx = fmaxf(mx, __shfl_xor_sync(~0u, mx, o));
  if ((tid & 31) == 0) sm[tid >> 5] = mx;
  __syncthreads();
  if (tid < 32) {
    float t = (tid < 8) ? sm[tid] : -1e30f;
    #pragma unroll
    for (int o = 4; o > 0; o >>= 1) t = fmaxf(t, __shfl_xor_sync(~0u, t, o));
    if (tid == 0) sm[0] = t;
  }
  __syncthreads();
  mx = sm[0];

  float sum = 0.0f;
  #pragma unroll
  for (int i = 0; i < 8; i++) { loc[i] = expf(loc[i] - mx); sum += loc[i]; }
  __shared__ float ss[8];
  #pragma unroll
  for (int o = 16; o > 0; o >>= 1) sum += __shfl_xor_sync(~0u, sum, o);
  if ((tid & 31) == 0) ss[tid >> 5] = sum;
  __syncthreads();
  if (tid < 32) {
    float t = (tid < 8) ? ss[tid] : 0.0f;
    #pragma unroll
    for (int o = 4; o > 0; o >>= 1) t += __shfl_xor_sync(~0u, t, o);
    if (tid == 0) ss[0] = t;
  }
  __syncthreads();
  const float inv = 1.0f / ss[0];
  #pragma unroll
  for (int i = 0; i < 8; i++)
    out[(long long)bq * SDIM + i * 256 + tid] = loc[i] * inv;
}

// ----------------------------------------------------------------- launch
extern "C" void kernel_launch(void* const* d_in, const int* in_sizes, int n_in,
                              void* d_out, int out_size) {
  const float* hidden = nullptr;
  const float* enc    = nullptr;
  const int*   mask   = nullptr;
  const float* W      = nullptr;
  const float* b_attn = nullptr;
  const float* v      = nullptr;

  // pass 1: element counts; pass 2: byte counts (all dtypes here are 4 bytes)
  for (int pass = 0; pass < 2; pass++) {
    const long long mul = (pass == 0) ? 1LL : 4LL;
    hidden = enc = W = b_attn = v = nullptr; mask = nullptr;
    for (int i = 0; i < n_in; i++) {
      const long long sz = (long long)in_sizes[i];
      if      (sz == 65536LL * mul)     hidden = (const float*)d_in[i];
      else if (sz == 268435456LL * mul) enc    = (const float*)d_in[i];
      else if (sz == 131072LL * mul)    mask   = (const int*)  d_in[i];
      else if (sz == 3145728LL * mul)   W      = (const float*)d_in[i];
      else if (sz == 1024LL * mul) {
        if (!b_attn) b_attn = (const float*)d_in[i];
        else         v      = (const float*)d_in[i];
      }
    }
    if (hidden && enc && mask && W && b_attn && v) break;
  }
  // pass 3: positional fallback (setup_inputs dict order)
  if (!hidden || !enc || !mask || !W || !b_attn || !v) {
    hidden = (const float*)d_in[0];
    enc    = (const float*)d_in[1];
    mask   = (const int*)  d_in[2];
    W      = (const float*)d_in[3];
    b_attn = (const float*)d_in[4];
    v      = (const float*)d_in[5];
  }
  float* out = (float*)d_out;   // (B,S) float32

  hwh_kernel<<<dim3(4, BDIM), 256>>>(hidden, W, b_attn);
  energy_simple_kernel<<<dim3(16, 2048), 256>>>(enc, W, v);
  softmax_kernel<<<BDIM, 256>>>(mask, out);
}

// round 6
// speedup vs baseline: 4.3353x; 4.3353x over previous
#include <cuda_runtime.h>
#include <cuda_bf16.h>
#include <cstdint>
#include <math.h>

#define BDIM 64
#define SDIM 2048
#define HDIM 1024
#define KDIM 2048   // 2H (contraction)
#define NDIM 1024   // H  (energy dim)

#define BM 128
#define BN 128
#define BK 16
#define PADA 20     // 80B row pitch (16B multiple)
#define PADB 136    // 544B row pitch (16B multiple)

// scratch (allocation-free rule: __device__ globals)
__device__ float g_hWh[BDIM * NDIM];            // hidden@Wh + b_attn
__device__ float g_part[8 * BDIM * SDIM];       // per-nTile partial scores

// ---------------------------------------------------------------- helpers
__device__ __forceinline__ void cpa16(void* s, const void* g) {
  uint32_t sa = (uint32_t)__cvta_generic_to_shared(s);
  asm volatile("cp.async.cg.shared.global [%0], [%1], 16;\n" :: "r"(sa), "l"(g));
}
__device__ __forceinline__ uint32_t f2tf(float x) {
  uint32_t r;
  asm("cvt.rna.tf32.f32 %0, %1;" : "=r"(r) : "f"(x));
  return r;
}
__device__ __forceinline__ void mma8(float* d, const uint32_t* a, const uint32_t* b) {
  asm volatile(
    "mma.sync.aligned.m16n8k8.row.col.f32.tf32.tf32.f32 "
    "{%0,%1,%2,%3}, {%4,%5,%6,%7}, {%8,%9}, {%0,%1,%2,%3};\n"
    : "+f"(d[0]), "+f"(d[1]), "+f"(d[2]), "+f"(d[3])
    : "r"(a[0]), "r"(a[1]), "r"(a[2]), "r"(a[3]), "r"(b[0]), "r"(b[1]));
}

// ------------------------------------------------- kernel 1: hWh + b_attn
__global__ void hwh_kernel(const float* __restrict__ hidden,
                           const float* __restrict__ W,
                           const float* __restrict__ b_attn) {
  const int n = blockIdx.x * 256 + threadIdx.x;   // grid.x = 4
  const int b = blockIdx.y;                       // grid.y = 64
  float acc = b_attn[n];
  const float* hrow = hidden + (long long)b * HDIM;
  for (int h = 0; h < HDIM; h++)
    acc = fmaf(hrow[h], W[(long long)h * NDIM + n], acc);   // Wh = W_attn[:H]
  g_hWh[(long long)b * NDIM + n] = acc;
}

// ------------------------------------------------ tile loader (cp.async)
__device__ __forceinline__ void load_tile(float (*As)[PADA], float (*Bs)[PADB],
                                          const float* Abase, const float* Bbase,
                                          int k0, int tid) {
  #pragma unroll
  for (int i = 0; i < 2; i++) {                // A: 128x16 fp32 = 512 x 16B
    int c = tid * 2 + i;
    int r = c >> 2, q = c & 3;
    cpa16(&As[r][q * 4], Abase + (size_t)r * KDIM + k0 + q * 4);
  }
  #pragma unroll
  for (int i = 0; i < 2; i++) {                // B: 16x128 fp32 = 512 x 16B
    int c = tid * 2 + i;
    int r = c >> 5, q = c & 31;
    cpa16(&Bs[r][q * 4], Bbase + (size_t)(k0 + r) * NDIM + q * 4);
  }
  asm volatile("cp.async.commit_group;\n" ::: "memory");
}

// ------------------- kernel 2: fused E = enc@We ; p = sum_n v*tanh(E+hWh)
__global__ __launch_bounds__(256, 2)
void energy_gemm_kernel(const float* __restrict__ enc,
                        const float* __restrict__ W,
                        const float* __restrict__ v) {
  __shared__ __align__(16) float As[2][BM][PADA];
  __shared__ __align__(16) float Bs[2][BK][PADB];
  __shared__ __align__(16) float s_hwh[BN];
  __shared__ __align__(16) float s_v[BN];
  __shared__ __align__(16) float s_red[2][BM];

  const int tid  = threadIdx.x;
  const int lane = tid & 31;
  const int wid  = tid >> 5;
  const int wm   = wid & 3;    // warp grid 4(M) x 2(N)
  const int wn   = wid >> 2;
  const int grp  = lane >> 2;  // 0..7
  const int qp   = lane & 3;   // 0..3

  const int mt  = blockIdx.y;            // 0..1023 (m-tile over B*S)
  const int n0  = blockIdx.x * BN;       // x fastest => L2 reuse of A across n
  const long long row0 = (long long)mt * BM;
  const int bidx = mt >> 4;              // 16 m-tiles per batch row

  const float* Abase = enc + (size_t)row0 * KDIM;
  const float* Bbase = W + (size_t)HDIM * NDIM + n0;   // We = W_attn[H:]

  float acc[2][8][4];
  #pragma unroll
  for (int i = 0; i < 2; i++)
    #pragma unroll
    for (int j = 0; j < 8; j++)
      #pragma unroll
      for (int e = 0; e < 4; e++) acc[i][j][e] = 0.f;

  const int KT = KDIM / BK;  // 128
  load_tile(As[0], Bs[0], Abase, Bbase, 0, tid);

  for (int kt = 0; kt < KT; kt++) {
    const int cur = kt & 1;
    if (kt + 1 < KT) {
      load_tile(As[cur ^ 1], Bs[cur ^ 1], Abase, Bbase, (kt + 1) * BK, tid);
      asm volatile("cp.async.wait_group 1;\n" ::: "memory");
    } else {
      asm volatile("cp.async.wait_group 0;\n" ::: "memory");
    }
    __syncthreads();

    #pragma unroll
    for (int ks = 0; ks < 2; ks++) {
      const int k0 = ks * 8;
      uint32_t a[2][4];
      #pragma unroll
      for (int mf = 0; mf < 2; mf++) {
        const int rm = wm * 32 + mf * 16;
        // PTX m16n8k8 tf32 A frag: a0:(g,t) a1:(g+8,t) a2:(g,t+4) a3:(g+8,t+4)
        a[mf][0] = f2tf(As[cur][rm + grp    ][k0 + qp    ]);
        a[mf][1] = f2tf(As[cur][rm + grp + 8][k0 + qp    ]);
        a[mf][2] = f2tf(As[cur][rm + grp    ][k0 + qp + 4]);
        a[mf][3] = f2tf(As[cur][rm + grp + 8][k0 + qp + 4]);
      }
      uint32_t bbf[8][2];
      #pragma unroll
      for (int nf = 0; nf < 8; nf++) {
        const int nc = wn * 64 + nf * 8 + grp;
        // B frag: b0:(k=t,n=g) b1:(k=t+4,n=g)
        bbf[nf][0] = f2tf(Bs[cur][k0 + qp    ][nc]);
        bbf[nf][1] = f2tf(Bs[cur][k0 + qp + 4][nc]);
      }
      #pragma unroll
      for (int mf = 0; mf < 2; mf++)
        #pragma unroll
        for (int nf = 0; nf < 8; nf++)
          mma8(acc[mf][nf], a[mf], bbf[nf]);
    }
    __syncthreads();
  }

  // ---------------- epilogue: + hWh, tanh, dot v, reduce over this n-tile
  if (tid < BN) {
    s_hwh[tid] = g_hWh[(size_t)bidx * NDIM + n0 + tid];
    s_v[tid]   = v[n0 + tid];
  }
  __syncthreads();

  float p[2][2] = {{0.f, 0.f}, {0.f, 0.f}};
  #pragma unroll
  for (int mf = 0; mf < 2; mf++)
    #pragma unroll
    for (int nf = 0; nf < 8; nf++)
      #pragma unroll
      for (int e = 0; e < 4; e++) {
        // C frag: d0:(g,2t) d1:(g,2t+1) d2:(g+8,2t) d3:(g+8,2t+1)
        const int nl = wn * 64 + nf * 8 + qp * 2 + (e & 1);
        const float en = tanhf(acc[mf][nf][e] + s_hwh[nl]);
        p[mf][e >> 1] += en * s_v[nl];
      }
  #pragma unroll
  for (int mf = 0; mf < 2; mf++)
    #pragma unroll
    for (int h = 0; h < 2; h++) {
      float x = p[mf][h];
      x += __shfl_xor_sync(0xffffffffu, x, 1);
      x += __shfl_xor_sync(0xffffffffu, x, 2);
      if (qp == 0) s_red[wn][wm * 32 + mf * 16 + h * 8 + grp] = x;
    }
  __syncthreads();
  if (tid < BM)
    g_part[(size_t)blockIdx.x * (BDIM * SDIM) + row0 + tid] =
        s_red[0][tid] + s_red[1][tid];
}

// ------------------------------------------ kernel 3: mask + softmax(S)
__global__ void softmax_kernel(const int* __restrict__ mask,
                               float* __restrict__ out) {
  const int bq = blockIdx.x;     // 0..63
  const int tid = threadIdx.x;   // 256
  float loc[8];
  float mx = -1e30f;
  #pragma unroll
  for (int i = 0; i < 8; i++) {
    const long long idx = (long long)bq * SDIM + i * 256 + tid;
    float sc = 0.0f;
    #pragma unroll
    for (int j = 0; j < 8; j++) sc += g_part[(long long)j * (BDIM * SDIM) + idx];
    if (mask[idx] == 0) sc = -1e9f;
    loc[i] = sc;
    mx = fmaxf(mx, sc);
  }
  __shared__ float sm[8];
  #pragma unroll
  for (int o = 16; o > 0; o >>= 1) mx = fmaxf(mx, __shfl_xor_sync(~0u, mx, o));
  if ((tid & 31) == 0) sm[tid >> 5] = mx;
  __syncthreads();
  if (tid < 32) {
    float t = (tid < 8) ? sm[tid] : -1e30f;
    #pragma unroll
    for (int o = 4; o > 0; o >>= 1) t = fmaxf(t, __shfl_xor_sync(~0u, t, o));
    if (tid == 0) sm[0] = t;
  }
  __syncthreads();
  mx = sm[0];

  float sum = 0.0f;
  #pragma unroll
  for (int i = 0; i < 8; i++) { loc[i] = expf(loc[i] - mx); sum += loc[i]; }
  __shared__ float ss[8];
  #pragma unroll
  for (int o = 16; o > 0; o >>= 1) sum += __shfl_xor_sync(~0u, sum, o);
  if ((tid & 31) == 0) ss[tid >> 5] = sum;
  __syncthreads();
  if (tid < 32) {
    float t = (tid < 8) ? ss[tid] : 0.0f;
    #pragma unroll
    for (int o = 4; o > 0; o >>= 1) t += __shfl_xor_sync(~0u, t, o);
    if (tid == 0) ss[0] = t;
  }
  __syncthreads();
  const float inv = 1.0f / ss[0];
  #pragma unroll
  for (int i = 0; i < 8; i++)
    out[(long long)bq * SDIM + i * 256 + tid] = loc[i] * inv;
}

// ----------------------------------------------------------------- launch
extern "C" void kernel_launch(void* const* d_in, const int* in_sizes, int n_in,
                              void* d_out, int out_size) {
  const float* hidden = nullptr;
  const float* enc    = nullptr;
  const int*   mask   = nullptr;
  const float* W      = nullptr;
  const float* b_attn = nullptr;
  const float* v      = nullptr;

  // pass 1: element counts; pass 2: byte counts (all dtypes here are 4 bytes)
  for (int pass = 0; pass < 2; pass++) {
    const long long mul = (pass == 0) ? 1LL : 4LL;
    hidden = enc = W = b_attn = v = nullptr; mask = nullptr;
    for (int i = 0; i < n_in; i++) {
      const long long sz = (long long)in_sizes[i];
      if      (sz == 65536LL * mul)     hidden = (const float*)d_in[i];
      else if (sz == 268435456LL * mul) enc    = (const float*)d_in[i];
      else if (sz == 131072LL * mul)    mask   = (const int*)  d_in[i];
      else if (sz == 3145728LL * mul)   W      = (const float*)d_in[i];
      else if (sz == 1024LL * mul) {
        if (!b_attn) b_attn = (const float*)d_in[i];
        else         v      = (const float*)d_in[i];
      }
    }
    if (hidden && enc && mask && W && b_attn && v) break;
  }
  // pass 3: positional fallback (setup_inputs dict order)
  if (!hidden || !enc || !mask || !W || !b_attn || !v) {
    hidden = (const float*)d_in[0];
    enc    = (const float*)d_in[1];
    mask   = (const int*)  d_in[2];
    W      = (const float*)d_in[3];
    b_attn = (const float*)d_in[4];
    v      = (const float*)d_in[5];
  }
  float* out = (float*)d_out;   // (B,S) float32

  hwh_kernel<<<dim3(4, BDIM), 256>>>(hidden, W, b_attn);
  energy_gemm_kernel<<<dim3(8, 1024), 256>>>(enc, W, v);
  softmax_kernel<<<BDIM, 256>>>(mask, out);
}

// round 8
// speedup vs baseline: 7.0079x; 1.6165x over previous
#include <cuda_runtime.h>
#include <cuda_fp16.h>
#include <cstdint>
#include <math.h>

#define BDIM 64
#define SDIM 2048
#define HDIM 1024
#define KDIM 2048   // 2H (contraction)
#define NDIM 1024   // H  (energy dim)

#define BM 128
#define BN 128
#define BK 32        // halves per k-tile
#define PADH 40      // row pitch in halves (80B: 16B multiple, conflict-free)

// ---- device scratch (allocation-free rule: __device__ globals) ----
__device__ float  g_hWh[BDIM * NDIM];               // hidden@Wh + b_attn
__device__ float  g_part[8 * BDIM * SDIM];          // per-nTile partial scores
__device__ __half g_encH[(size_t)BDIM * SDIM * KDIM];  // enc in fp16 (512MB)
__device__ __half g_WhT[(size_t)NDIM * KDIM];          // We^T in fp16 [N][K] (4MB)

// ---------------------------------------------------------------- helpers
__device__ __forceinline__ void cpa16(void* s, const void* g) {
  uint32_t sa = (uint32_t)__cvta_generic_to_shared(s);
  asm volatile("cp.async.cg.shared.global [%0], [%1], 16;\n" :: "r"(sa), "l"(g));
}
__device__ __forceinline__ void mma16(float* d, const uint32_t* a, const uint32_t* b) {
  asm volatile(
    "mma.sync.aligned.m16n8k16.row.col.f32.f16.f16.f32 "
    "{%0,%1,%2,%3}, {%4,%5,%6,%7}, {%8,%9}, {%0,%1,%2,%3};\n"
    : "+f"(d[0]), "+f"(d[1]), "+f"(d[2]), "+f"(d[3])
    : "r"(a[0]), "r"(a[1]), "r"(a[2]), "r"(a[3]), "r"(b[0]), "r"(b[1]));
}

// --------------------------------------- kernel 0a: enc (fp32) -> fp16
__global__ void enc2h_kernel(const float4* __restrict__ enc4) {
  __half2* out = (__half2*)g_encH;
  const size_t total = (size_t)BDIM * SDIM * KDIM / 4;   // float4 count
  for (size_t i = (size_t)blockIdx.x * blockDim.x + threadIdx.x; i < total;
       i += (size_t)gridDim.x * blockDim.x) {
    float4 x = enc4[i];
    out[i * 2]     = __float22half2_rn(make_float2(x.x, x.y));
    out[i * 2 + 1] = __float22half2_rn(make_float2(x.z, x.w));
  }
}

// ----------------------- kernel 0b: WhT[n][k] = fp16(W[H+k][n]) transpose
__global__ void wt_kernel(const float* __restrict__ W) {
  __shared__ float t[32][33];
  const int n0 = blockIdx.x * 32;
  const int k0 = blockIdx.y * 32;
  const int tx = threadIdx.x, ty = threadIdx.y;   // 32 x 8
  #pragma unroll
  for (int i = 0; i < 4; i++)
    t[ty + i * 8][tx] = W[(size_t)(HDIM + k0 + ty + i * 8) * NDIM + n0 + tx];
  __syncthreads();
  #pragma unroll
  for (int i = 0; i < 4; i++)
    g_WhT[(size_t)(n0 + ty + i * 8) * KDIM + k0 + tx] =
        __float2half_rn(t[tx][ty + i * 8]);
}

// ------------------------------------------------- kernel 1: hWh + b_attn
__global__ void hwh_kernel(const float* __restrict__ hidden,
                           const float* __restrict__ W,
                           const float* __restrict__ b_attn) {
  const int n = blockIdx.x * 256 + threadIdx.x;   // grid.x = 4
  const int b = blockIdx.y;                       // grid.y = 64
  float acc = b_attn[n];
  const float* hrow = hidden + (long long)b * HDIM;
  for (int h = 0; h < HDIM; h++)
    acc = fmaf(hrow[h], W[(long long)h * NDIM + n], acc);   // Wh = W_attn[:H]
  g_hWh[(long long)b * NDIM + n] = acc;
}

// ------------------------------------------------ tile loader (cp.async)
// A: 128 rows x 64B (4 chunks) ; B: 128 rows x 64B — 512 chunks each, 2/thread
__device__ __forceinline__ void load_tile(__half (*As)[PADH], __half (*Bs)[PADH],
                                          const __half* Ag, const __half* Bg,
                                          int kh, int tid) {
  #pragma unroll
  for (int i = 0; i < 2; i++) {
    int c = tid * 2 + i;
    int r = c >> 2, q = c & 3;
    cpa16(&As[r][q * 8], Ag + (size_t)r * KDIM + kh + q * 8);
    cpa16(&Bs[r][q * 8], Bg + (size_t)r * KDIM + kh + q * 8);
  }
  asm volatile("cp.async.commit_group;\n" ::: "memory");
}

// ------------- kernel 2: fused E = enc@We (fp16 MMA) ; p = v·tanh(E+hWh)
__global__ __launch_bounds__(256, 2)
void energy_fp16_kernel(const float* __restrict__ v) {
  __shared__ __align__(16) __half As[2][BM][PADH];
  __shared__ __align__(16) __half Bs[2][BN][PADH];
  __shared__ __align__(16) float s_hwh[BN];
  __shared__ __align__(16) float s_v[BN];
  __shared__ __align__(16) float s_red[2][BM];

  const int tid  = threadIdx.x;
  const int lane = tid & 31;
  const int wid  = tid >> 5;
  const int wm   = wid & 3;    // warp grid 4(M) x 2(N)
  const int wn   = wid >> 2;
  const int grp  = lane >> 2;  // 0..7
  const int qp   = lane & 3;   // 0..3

  const int mt  = blockIdx.y;            // 0..1023 (m-tile over B*S)
  const int n0  = blockIdx.x * BN;       // x fastest => L2 reuse of A across n
  const size_t row0 = (size_t)mt * BM;
  const int bidx = mt >> 4;              // 16 m-tiles per batch row

  const __half* Ag = g_encH + row0 * KDIM;
  const __half* Bg = g_WhT + (size_t)n0 * KDIM;

  float acc[2][8][4];
  #pragma unroll
  for (int i = 0; i < 2; i++)
    #pragma unroll
    for (int j = 0; j < 8; j++)
      #pragma unroll
      for (int e = 0; e < 4; e++) acc[i][j][e] = 0.f;

  const int KT = KDIM / BK;  // 64
  load_tile(As[0], Bs[0], Ag, Bg, 0, tid);

  for (int kt = 0; kt < KT; kt++) {
    const int cur = kt & 1;
    if (kt + 1 < KT) {
      load_tile(As[cur ^ 1], Bs[cur ^ 1], Ag, Bg, (kt + 1) * BK, tid);
      asm volatile("cp.async.wait_group 1;\n" ::: "memory");
    } else {
      asm volatile("cp.async.wait_group 0;\n" ::: "memory");
    }
    __syncthreads();

    #pragma unroll
    for (int ks = 0; ks < 2; ks++) {
      const int kh = ks * 16;   // half-offset of this k16 step
      // A frag (m16n8k16): reg0=A[g][2t,2t+1] reg1=A[g+8][..] reg2=A[g][2t+8,+9] reg3=A[g+8][..]
      uint32_t a[2][4];
      #pragma unroll
      for (int mf = 0; mf < 2; mf++) {
        const int r0 = wm * 32 + mf * 16 + grp;
        a[mf][0] = *(const uint32_t*)&As[cur][r0    ][kh + qp * 2];
        a[mf][1] = *(const uint32_t*)&As[cur][r0 + 8][kh + qp * 2];
        a[mf][2] = *(const uint32_t*)&As[cur][r0    ][kh + qp * 2 + 8];
        a[mf][3] = *(const uint32_t*)&As[cur][r0 + 8][kh + qp * 2 + 8];
      }
      // B frag: reg0=B^T[n=g][k=2t,2t+1] reg1=B^T[n=g][k=2t+8,+9]
      uint32_t b[8][2];
      #pragma unroll
      for (int nf = 0; nf < 8; nf++) {
        const int nr = wn * 64 + nf * 8 + grp;
        b[nf][0] = *(const uint32_t*)&Bs[cur][nr][kh + qp * 2];
        b[nf][1] = *(const uint32_t*)&Bs[cur][nr][kh + qp * 2 + 8];
      }
      #pragma unroll
      for (int mf = 0; mf < 2; mf++)
        #pragma unroll
        for (int nf = 0; nf < 8; nf++)
          mma16(acc[mf][nf], a[mf], b[nf]);
    }
    __syncthreads();
  }

  // ---------------- epilogue: + hWh, tanh, dot v, reduce over this n-tile
  if (tid < BN) {
    s_hwh[tid] = g_hWh[(size_t)bidx * NDIM + n0 + tid];
    s_v[tid]   = v[n0 + tid];
  }
  __syncthreads();

  float p[2][2] = {{0.f, 0.f}, {0.f, 0.f}};
  #pragma unroll
  for (int mf = 0; mf < 2; mf++)
    #pragma unroll
    for (int nf = 0; nf < 8; nf++)
      #pragma unroll
      for (int e = 0; e < 4; e++) {
        // C frag: d0:(g,2t) d1:(g,2t+1) d2:(g+8,2t) d3:(g+8,2t+1)
        const int nl = wn * 64 + nf * 8 + qp * 2 + (e & 1);
        const float en = tanhf(acc[mf][nf][e] + s_hwh[nl]);
        p[mf][e >> 1] += en * s_v[nl];
      }
  #pragma unroll
  for (int mf = 0; mf < 2; mf++)
    #pragma unroll
    for (int h = 0; h < 2; h++) {
      float x = p[mf][h];
      x += __shfl_xor_sync(0xffffffffu, x, 1);
      x += __shfl_xor_sync(0xffffffffu, x, 2);
      if (qp == 0) s_red[wn][wm * 32 + mf * 16 + h * 8 + grp] = x;
    }
  __syncthreads();
  if (tid < BM)
    g_part[(size_t)blockIdx.x * (BDIM * SDIM) + row0 + tid] =
        s_red[0][tid] + s_red[1][tid];
}

// ------------------------------------------ kernel 3: mask + softmax(S)
__global__ void softmax_kernel(const int* __restrict__ mask,
                               float* __restrict__ out) {
  const int bq = blockIdx.x;     // 0..63
  const int tid = threadIdx.x;   // 256
  float loc[8];
  float mx = -1e30f;
  #pragma unroll
  for (int i = 0; i < 8; i++) {
    const long long idx = (long long)bq * SDIM + i * 256 + tid;
    float sc = 0.0f;
    #pragma unroll
    for (int j = 0; j < 8; j++) sc += g_part[(long long)j * (BDIM * SDIM) + idx];
    if (mask[idx] == 0) sc = -1e9f;
    loc[i] = sc;
    mx = fmaxf(mx, sc);
  }
  __shared__ float sm[8];
  #pragma unroll
  for (int o = 16; o > 0; o >>= 1) mx = fmaxf(mx, __shfl_xor_sync(~0u, mx, o));
  if ((tid & 31) == 0) sm[tid >> 5] = mx;
  __syncthreads();
  if (tid < 32) {
    float t = (tid < 8) ? sm[tid] : -1e30f;
    #pragma unroll
    for (int o = 4; o > 0; o >>= 1) t = fmaxf(t, __shfl_xor_sync(~0u, t, o));
    if (tid == 0) sm[0] = t;
  }
  __syncthreads();
  mx = sm[0];

  float sum = 0.0f;
  #pragma unroll
  for (int i = 0; i < 8; i++) { loc[i] = expf(loc[i] - mx); sum += loc[i]; }
  __shared__ float ss[8];
  #pragma unroll
  for (int o = 16; o > 0; o >>= 1) sum += __shfl_xor_sync(~0u, sum, o);
  if ((tid & 31) == 0) ss[tid >> 5] = sum;
  __syncthreads();
  if (tid < 32) {
    float t = (tid < 8) ? ss[tid] : 0.0f;
    #pragma unroll
    for (int o = 4; o > 0; o >>= 1) t += __shfl_xor_sync(~0u, t, o);
    if (tid == 0) ss[0] = t;
  }
  __syncthreads();
  const float inv = 1.0f / ss[0];
  #pragma unroll
  for (int i = 0; i < 8; i++)
    out[(long long)bq * SDIM + i * 256 + tid] = loc[i] * inv;
}

// ----------------------------------------------------------------- launch
extern "C" void kernel_launch(void* const* d_in, const int* in_sizes, int n_in,
                              void* d_out, int out_size) {
  const float* hidden = nullptr;
  const float* enc    = nullptr;
  const int*   mask   = nullptr;
  const float* W      = nullptr;
  const float* b_attn = nullptr;
  const float* v      = nullptr;

  // pass 1: element counts; pass 2: byte counts (all dtypes here are 4 bytes)
  for (int pass = 0; pass < 2; pass++) {
    const long long mul = (pass == 0) ? 1LL : 4LL;
    hidden = enc = W = b_attn = v = nullptr; mask = nullptr;
    for (int i = 0; i < n_in; i++) {
      const long long sz = (long long)in_sizes[i];
      if      (sz == 65536LL * mul)     hidden = (const float*)d_in[i];
      else if (sz == 268435456LL * mul) enc    = (const float*)d_in[i];
      else if (sz == 131072LL * mul)    mask   = (const int*)  d_in[i];
      else if (sz == 3145728LL * mul)   W      = (const float*)d_in[i];
      else if (sz == 1024LL * mul) {
        if (!b_attn) b_attn = (const float*)d_in[i];
        else         v      = (const float*)d_in[i];
      }
    }
    if (hidden && enc && mask && W && b_attn && v) break;
  }
  // pass 3: positional fallback (setup_inputs dict order)
  if (!hidden || !enc || !mask || !W || !b_attn || !v) {
    hidden = (const float*)d_in[0];
    enc    = (const float*)d_in[1];
    mask   = (const int*)  d_in[2];
    W      = (const float*)d_in[3];
    b_attn = (const float*)d_in[4];
    v      = (const float*)d_in[5];
  }
  float* out = (float*)d_out;   // (B,S) float32

  enc2h_kernel<<<8192, 256>>>((const float4*)enc);
  wt_kernel<<<dim3(32, 64), dim3(32, 8)>>>(W);
  hwh_kernel<<<dim3(4, BDIM), 256>>>(hidden, W, b_attn);
  energy_fp16_kernel<<<dim3(8, 1024), 256>>>(v);
  softmax_kernel<<<BDIM, 256>>>(mask, out);
}

// round 9
// speedup vs baseline: 7.8059x; 1.1139x over previous
#include <cuda_runtime.h>
#include <cuda_fp16.h>
#include <cstdint>
#include <math.h>

#define BDIM 64
#define SDIM 2048
#define HDIM 1024
#define KDIM 2048   // 2H (contraction)
#define NDIM 1024   // H  (energy dim)

#define BM 128
#define BN 128
#define BK 32        // halves per k-tile
#define PADH 40      // row pitch in halves (80B: 16B multiple, conflict-free LDSM)

// ---- device scratch (allocation-free rule: __device__ globals) ----
__device__ float  g_hWh[BDIM * NDIM];               // hidden@Wh + b_attn
__device__ float  g_part[8 * BDIM * SDIM];          // per-nTile partial scores
__device__ __half g_encH[(size_t)BDIM * SDIM * KDIM];  // enc in fp16 (512MB)
__device__ __half g_WhT[(size_t)NDIM * KDIM];          // We^T in fp16 [N][K] (4MB)

// ---------------------------------------------------------------- helpers
__device__ __forceinline__ void cpa16(void* s, const void* g) {
  uint32_t sa = (uint32_t)__cvta_generic_to_shared(s);
  asm volatile("cp.async.cg.shared.global [%0], [%1], 16;\n" :: "r"(sa), "l"(g));
}
__device__ __forceinline__ uint32_t smem_u32(const void* p) {
  uint32_t a;
  asm("{ .reg .u64 t; cvta.to.shared.u64 t, %1; cvt.u32.u64 %0, t; }" : "=r"(a) : "l"(p));
  return a;
}
__device__ __forceinline__ void mma16(float* d, const uint32_t* a, const uint32_t* b) {
  asm volatile(
    "mma.sync.aligned.m16n8k16.row.col.f32.f16.f16.f32 "
    "{%0,%1,%2,%3}, {%4,%5,%6,%7}, {%8,%9}, {%0,%1,%2,%3};\n"
    : "+f"(d[0]), "+f"(d[1]), "+f"(d[2]), "+f"(d[3])
    : "r"(a[0]), "r"(a[1]), "r"(a[2]), "r"(a[3]), "r"(b[0]), "r"(b[1]));
}
__device__ __forceinline__ void ldsm4(uint32_t& r0, uint32_t& r1,
                                      uint32_t& r2, uint32_t& r3, uint32_t addr) {
  asm volatile("ldmatrix.sync.aligned.m8n8.x4.shared.b16 {%0,%1,%2,%3}, [%4];"
               : "=r"(r0), "=r"(r1), "=r"(r2), "=r"(r3) : "r"(addr));
}

// --------------------------------------- kernel 0a: enc (fp32) -> fp16
__global__ void enc2h_kernel(const float4* __restrict__ enc4) {
  __half2* out = (__half2*)g_encH;
  const size_t total = (size_t)BDIM * SDIM * KDIM / 4;   // float4 count
  for (size_t i = (size_t)blockIdx.x * blockDim.x + threadIdx.x; i < total;
       i += (size_t)gridDim.x * blockDim.x) {
    float4 x = enc4[i];
    out[i * 2]     = __float22half2_rn(make_float2(x.x, x.y));
    out[i * 2 + 1] = __float22half2_rn(make_float2(x.z, x.w));
  }
}

// ----------------------- kernel 0b: WhT[n][k] = fp16(W[H+k][n]) transpose
__global__ void wt_kernel(const float* __restrict__ W) {
  __shared__ float t[32][33];
  const int n0 = blockIdx.x * 32;
  const int k0 = blockIdx.y * 32;
  const int tx = threadIdx.x, ty = threadIdx.y;   // 32 x 8
  #pragma unroll
  for (int i = 0; i < 4; i++)
    t[ty + i * 8][tx] = W[(size_t)(HDIM + k0 + ty + i * 8) * NDIM + n0 + tx];
  __syncthreads();
  #pragma unroll
  for (int i = 0; i < 4; i++)
    g_WhT[(size_t)(n0 + ty + i * 8) * KDIM + k0 + tx] =
        __float2half_rn(t[tx][ty + i * 8]);
}

// ------------------------------------------------- kernel 1: hWh + b_attn
__global__ void hwh_kernel(const float* __restrict__ hidden,
                           const float* __restrict__ W,
                           const float* __restrict__ b_attn) {
  const int n = blockIdx.x * 256 + threadIdx.x;   // grid.x = 4
  const int b = blockIdx.y;                       // grid.y = 64
  float acc = b_attn[n];
  const float* hrow = hidden + (long long)b * HDIM;
  for (int h = 0; h < HDIM; h++)
    acc = fmaf(hrow[h], W[(long long)h * NDIM + n], acc);   // Wh = W_attn[:H]
  g_hWh[(long long)b * NDIM + n] = acc;
}

// ------------------------------------------------ tile loader (cp.async)
__device__ __forceinline__ void load_tile(__half (*As)[PADH], __half (*Bs)[PADH],
                                          const __half* Ag, const __half* Bg,
                                          int kh, int tid) {
  #pragma unroll
  for (int i = 0; i < 2; i++) {
    int c = tid * 2 + i;
    int r = c >> 2, q = c & 3;
    cpa16(&As[r][q * 8], Ag + (size_t)r * KDIM + kh + q * 8);
    cpa16(&Bs[r][q * 8], Bg + (size_t)r * KDIM + kh + q * 8);
  }
  asm volatile("cp.async.commit_group;\n" ::: "memory");
}

// ------------- kernel 2: fused E = enc@We (fp16 MMA) ; p = v·tanh(E+hWh)
__global__ __launch_bounds__(256, 2)
void energy_fp16_kernel(const float* __restrict__ v) {
  __shared__ __align__(16) __half As[2][BM][PADH];
  __shared__ __align__(16) __half Bs[2][BN][PADH];
  __shared__ __align__(16) float s_hwh[BN];
  __shared__ __align__(16) float s_v[BN];
  __shared__ __align__(16) float s_red[2][BM];

  const int tid  = threadIdx.x;
  const int lane = tid & 31;
  const int wid  = tid >> 5;
  const int wm   = wid & 3;    // warp grid 4(M) x 2(N)
  const int wn   = wid >> 2;
  const int grp  = lane >> 2;  // 0..7
  const int qp   = lane & 3;   // 0..3

  const int mt  = blockIdx.y;            // 0..1023 (m-tile over B*S)
  const int n0  = blockIdx.x * BN;       // x fastest => L2 reuse of A across n
  const size_t row0 = (size_t)mt * BM;
  const int bidx = mt >> 4;              // 16 m-tiles per batch row

  const __half* Ag = g_encH + row0 * KDIM;
  const __half* Bg = g_WhT + (size_t)n0 * KDIM;

  // ---- ldmatrix per-lane byte offsets (within one tile buffer) ----
  const int l8 = lane & 7;        // row within 8x8 matrix
  const int lm = lane >> 3;       // matrix index 0..3
  // A x4: m0:(r, klo) m1:(r+8, klo) m2:(r, khi) m3:(r+8, khi)
  uint32_t aOff[2];
  #pragma unroll
  for (int mf = 0; mf < 2; mf++) {
    const int row = wm * 32 + mf * 16 + l8 + (lm & 1) * 8;
    const int col = (lm >> 1) * 8;
    aOff[mf] = (uint32_t)((row * PADH + col) * 2);
  }
  // B x4 (per nf-pair): m0:(n, klo) m1:(n, khi) m2:(n+8, klo) m3:(n+8, khi)
  uint32_t bOff[4];
  #pragma unroll
  for (int nfp = 0; nfp < 4; nfp++) {
    const int row = wn * 64 + nfp * 16 + l8 + (lm >> 1) * 8;
    const int col = (lm & 1) * 8;
    bOff[nfp] = (uint32_t)((row * PADH + col) * 2);
  }
  const uint32_t aBase[2] = {smem_u32(&As[0][0][0]), smem_u32(&As[1][0][0])};
  const uint32_t bBase[2] = {smem_u32(&Bs[0][0][0]), smem_u32(&Bs[1][0][0])};

  float acc[2][8][4];
  #pragma unroll
  for (int i = 0; i < 2; i++)
    #pragma unroll
    for (int j = 0; j < 8; j++)
      #pragma unroll
      for (int e = 0; e < 4; e++) acc[i][j][e] = 0.f;

  const int KT = KDIM / BK;  // 64
  load_tile(As[0], Bs[0], Ag, Bg, 0, tid);

  for (int kt = 0; kt < KT; kt++) {
    const int cur = kt & 1;
    if (kt + 1 < KT) {
      load_tile(As[cur ^ 1], Bs[cur ^ 1], Ag, Bg, (kt + 1) * BK, tid);
      asm volatile("cp.async.wait_group 1;\n" ::: "memory");
    } else {
      asm volatile("cp.async.wait_group 0;\n" ::: "memory");
    }
    __syncthreads();

    #pragma unroll
    for (int ks = 0; ks < 2; ks++) {
      const uint32_t kByte = (uint32_t)(ks * 16 * 2);   // k16 step offset
      uint32_t a[2][4];
      #pragma unroll
      for (int mf = 0; mf < 2; mf++)
        ldsm4(a[mf][0], a[mf][1], a[mf][2], a[mf][3],
              aBase[cur] + aOff[mf] + kByte);
      uint32_t b[8][2];
      #pragma unroll
      for (int nfp = 0; nfp < 4; nfp++)
        ldsm4(b[nfp * 2][0], b[nfp * 2][1], b[nfp * 2 + 1][0], b[nfp * 2 + 1][1],
              bBase[cur] + bOff[nfp] + kByte);
      #pragma unroll
      for (int mf = 0; mf < 2; mf++)
        #pragma unroll
        for (int nf = 0; nf < 8; nf++)
          mma16(acc[mf][nf], a[mf], b[nf]);
    }
    __syncthreads();
  }

  // ---------------- epilogue: + hWh, tanh, dot v, reduce over this n-tile
  if (tid < BN) {
    s_hwh[tid] = g_hWh[(size_t)bidx * NDIM + n0 + tid];
    s_v[tid]   = v[n0 + tid];
  }
  __syncthreads();

  float p[2][2] = {{0.f, 0.f}, {0.f, 0.f}};
  #pragma unroll
  for (int mf = 0; mf < 2; mf++)
    #pragma unroll
    for (int nf = 0; nf < 8; nf++)
      #pragma unroll
      for (int e = 0; e < 4; e++) {
        // C frag: d0:(g,2t) d1:(g,2t+1) d2:(g+8,2t) d3:(g+8,2t+1)
        const int nl = wn * 64 + nf * 8 + qp * 2 + (e & 1);
        const float en = tanhf(acc[mf][nf][e] + s_hwh[nl]);
        p[mf][e >> 1] += en * s_v[nl];
      }
  #pragma unroll
  for (int mf = 0; mf < 2; mf++)
    #pragma unroll
    for (int h = 0; h < 2; h++) {
      float x = p[mf][h];
      x += __shfl_xor_sync(0xffffffffu, x, 1);
      x += __shfl_xor_sync(0xffffffffu, x, 2);
      if (qp == 0) s_red[wn][wm * 32 + mf * 16 + h * 8 + grp] = x;
    }
  __syncthreads();
  if (tid < BM)
    g_part[(size_t)blockIdx.x * (BDIM * SDIM) + row0 + tid] =
        s_red[0][tid] + s_red[1][tid];
}

// ------------------------------------------ kernel 3: mask + softmax(S)
__global__ void softmax_kernel(const int* __restrict__ mask,
                               float* __restrict__ out) {
  const int bq = blockIdx.x;     // 0..63
  const int tid = threadIdx.x;   // 256
  float loc[8];
  float mx = -1e30f;
  #pragma unroll
  for (int i = 0; i < 8; i++) {
    const long long idx = (long long)bq * SDIM + i * 256 + tid;
    float sc = 0.0f;
    #pragma unroll
    for (int j = 0; j < 8; j++) sc += g_part[(long long)j * (BDIM * SDIM) + idx];
    if (mask[idx] == 0) sc = -1e9f;
    loc[i] = sc;
    mx = fmaxf(mx, sc);
  }
  __shared__ float sm[8];
  #pragma unroll
  for (int o = 16; o > 0; o >>= 1) mx = fmaxf(mx, __shfl_xor_sync(~0u, mx, o));
  if ((tid & 31) == 0) sm[tid >> 5] = mx;
  __syncthreads();
  if (tid < 32) {
    float t = (tid < 8) ? sm[tid] : -1e30f;
    #pragma unroll
    for (int o = 4; o > 0; o >>= 1) t = fmaxf(t, __shfl_xor_sync(~0u, t, o));
    if (tid == 0) sm[0] = t;
  }
  __syncthreads();
  mx = sm[0];

  float sum = 0.0f;
  #pragma unroll
  for (int i = 0; i < 8; i++) { loc[i] = expf(loc[i] - mx); sum += loc[i]; }
  __shared__ float ss[8];
  #pragma unroll
  for (int o = 16; o > 0; o >>= 1) sum += __shfl_xor_sync(~0u, sum, o);
  if ((tid & 31) == 0) ss[tid >> 5] = sum;
  __syncthreads();
  if (tid < 32) {
    float t = (tid < 8) ? ss[tid] : 0.0f;
    #pragma unroll
    for (int o = 4; o > 0; o >>= 1) t += __shfl_xor_sync(~0u, t, o);
    if (tid == 0) ss[0] = t;
  }
  __syncthreads();
  const float inv = 1.0f / ss[0];
  #pragma unroll
  for (int i = 0; i < 8; i++)
    out[(long long)bq * SDIM + i * 256 + tid] = loc[i] * inv;
}

// ----------------------------------------------------------------- launch
extern "C" void kernel_launch(void* const* d_in, const int* in_sizes, int n_in,
                              void* d_out, int out_size) {
  const float* hidden = nullptr;
  const float* enc    = nullptr;
  const int*   mask   = nullptr;
  const float* W      = nullptr;
  const float* b_attn = nullptr;
  const float* v      = nullptr;

  // pass 1: element counts; pass 2: byte counts (all dtypes here are 4 bytes)
  for (int pass = 0; pass < 2; pass++) {
    const long long mul = (pass == 0) ? 1LL : 4LL;
    hidden = enc = W = b_attn = v = nullptr; mask = nullptr;
    for (int i = 0; i < n_in; i++) {
      const long long sz = (long long)in_sizes[i];
      if      (sz == 65536LL * mul)     hidden = (const float*)d_in[i];
      else if (sz == 268435456LL * mul) enc    = (const float*)d_in[i];
      else if (sz == 131072LL * mul)    mask   = (const int*)  d_in[i];
      else if (sz == 3145728LL * mul)   W      = (const float*)d_in[i];
      else if (sz == 1024LL * mul) {
        if (!b_attn) b_attn = (const float*)d_in[i];
        else         v      = (const float*)d_in[i];
      }
    }
    if (hidden && enc && mask && W && b_attn && v) break;
  }
  // pass 3: positional fallback (setup_inputs dict order)
  if (!hidden || !enc || !mask || !W || !b_attn || !v) {
    hidden = (const float*)d_in[0];
    enc    = (const float*)d_in[1];
    mask   = (const int*)  d_in[2];
    W      = (const float*)d_in[3];
    b_attn = (const float*)d_in[4];
    v      = (const float*)d_in[5];
  }
  float* out = (float*)d_out;   // (B,S) float32

  enc2h_kernel<<<8192, 256>>>((const float4*)enc);
  wt_kernel<<<dim3(32, 64), dim3(32, 8)>>>(W);
  hwh_kernel<<<dim3(4, BDIM), 256>>>(hidden, W, b_attn);
  energy_fp16_kernel<<<dim3(8, 1024), 256>>>(v);
  softmax_kernel<<<BDIM, 256>>>(mask, out);
}

// round 10
// speedup vs baseline: 8.1092x; 1.0389x over previous
#include <cuda_runtime.h>
#include <cuda_fp16.h>
#include <cstdint>
#include <math.h>

#define BDIM 64
#define SDIM 2048
#define HDIM 1024
#define KDIM 2048   // 2H (contraction)
#define NDIM 1024   // H  (energy dim)

#define BM 128
#define BN 128
#define BK 32        // halves per k-tile
#define PADH 40      // row pitch in halves (80B: 16B multiple, conflict-free LDSM)
#define NST 4        // cp.async pipeline stages
#define STAGE_B (BM * PADH * 2)   // bytes per (A or B) stage = 10240

// ---- device scratch (allocation-free rule: __device__ globals) ----
__device__ float  g_hWh[BDIM * NDIM];               // hidden@Wh + b_attn
__device__ float  g_part[8 * BDIM * SDIM];          // per-nTile partial scores
__device__ __half g_encH[(size_t)BDIM * SDIM * KDIM];  // enc in fp16 (512MB)
__device__ __half g_WhT[(size_t)NDIM * KDIM];          // We^T in fp16 [N][K] (4MB)

// ---------------------------------------------------------------- helpers
__device__ __forceinline__ void cpa16(void* s, const void* g) {
  uint32_t sa = (uint32_t)__cvta_generic_to_shared(s);
  asm volatile("cp.async.cg.shared.global [%0], [%1], 16;\n" :: "r"(sa), "l"(g));
}
__device__ __forceinline__ uint32_t smem_u32(const void* p) {
  uint32_t a;
  asm("{ .reg .u64 t; cvta.to.shared.u64 t, %1; cvt.u32.u64 %0, t; }" : "=r"(a) : "l"(p));
  return a;
}
__device__ __forceinline__ void mma16(float* d, const uint32_t* a, const uint32_t* b) {
  asm volatile(
    "mma.sync.aligned.m16n8k16.row.col.f32.f16.f16.f32 "
    "{%0,%1,%2,%3}, {%4,%5,%6,%7}, {%8,%9}, {%0,%1,%2,%3};\n"
    : "+f"(d[0]), "+f"(d[1]), "+f"(d[2]), "+f"(d[3])
    : "r"(a[0]), "r"(a[1]), "r"(a[2]), "r"(a[3]), "r"(b[0]), "r"(b[1]));
}
__device__ __forceinline__ void ldsm4(uint32_t& r0, uint32_t& r1,
                                      uint32_t& r2, uint32_t& r3, uint32_t addr) {
  asm volatile("ldmatrix.sync.aligned.m8n8.x4.shared.b16 {%0,%1,%2,%3}, [%4];"
               : "=r"(r0), "=r"(r1), "=r"(r2), "=r"(r3) : "r"(addr));
}

// --------------------------------------- kernel 0a: enc (fp32) -> fp16
__global__ void enc2h_kernel(const float4* __restrict__ enc4) {
  __half2* out = (__half2*)g_encH;
  const size_t total = (size_t)BDIM * SDIM * KDIM / 4;
  for (size_t i = (size_t)blockIdx.x * blockDim.x + threadIdx.x; i < total;
       i += (size_t)gridDim.x * blockDim.x) {
    float4 x = enc4[i];
    out[i * 2]     = __float22half2_rn(make_float2(x.x, x.y));
    out[i * 2 + 1] = __float22half2_rn(make_float2(x.z, x.w));
  }
}

// ----------------------- kernel 0b: WhT[n][k] = fp16(W[H+k][n]) transpose
__global__ void wt_kernel(const float* __restrict__ W) {
  __shared__ float t[32][33];
  const int n0 = blockIdx.x * 32;
  const int k0 = blockIdx.y * 32;
  const int tx = threadIdx.x, ty = threadIdx.y;   // 32 x 8
  #pragma unroll
  for (int i = 0; i < 4; i++)
    t[ty + i * 8][tx] = W[(size_t)(HDIM + k0 + ty + i * 8) * NDIM + n0 + tx];
  __syncthreads();
  #pragma unroll
  for (int i = 0; i < 4; i++)
    g_WhT[(size_t)(n0 + ty + i * 8) * KDIM + k0 + tx] =
        __float2half_rn(t[tx][ty + i * 8]);
}

// ------------------------------------------------- kernel 1: hWh + b_attn
__global__ void hwh_kernel(const float* __restrict__ hidden,
                           const float* __restrict__ W,
                           const float* __restrict__ b_attn) {
  const int n = blockIdx.x * 256 + threadIdx.x;
  const int b = blockIdx.y;
  float acc = b_attn[n];
  const float* hrow = hidden + (long long)b * HDIM;
  for (int h = 0; h < HDIM; h++)
    acc = fmaf(hrow[h], W[(long long)h * NDIM + n], acc);
  g_hWh[(long long)b * NDIM + n] = acc;
}

// ------------------------------------------------ tile loader (cp.async)
__device__ __forceinline__ void load_tile(__half (*As)[PADH], __half (*Bs)[PADH],
                                          const __half* Ag, const __half* Bg,
                                          int kh, int tid) {
  #pragma unroll
  for (int i = 0; i < 2; i++) {
    int c = tid * 2 + i;
    int r = c >> 2, q = c & 3;
    cpa16(&As[r][q * 8], Ag + (size_t)r * KDIM + kh + q * 8);
    cpa16(&Bs[r][q * 8], Bg + (size_t)r * KDIM + kh + q * 8);
  }
  asm volatile("cp.async.commit_group;\n" ::: "memory");
}

// ------------- kernel 2: fused E = enc@We (fp16 MMA) ; p = v·tanh(E+hWh)
__global__ __launch_bounds__(256, 2)
void energy_fp16_kernel(const float* __restrict__ v) {
  extern __shared__ __align__(16) char dynsm[];
  __half (*As)[BM][PADH] = reinterpret_cast<__half(*)[BM][PADH]>(dynsm);
  __half (*Bs)[BM][PADH] = reinterpret_cast<__half(*)[BM][PADH]>(dynsm + NST * STAGE_B);
  float* s_hwh = (float*)(dynsm + 2 * NST * STAGE_B);
  float* s_v   = s_hwh + BN;
  float* s_red = s_v + BN;                 // [2][BM]

  const int tid  = threadIdx.x;
  const int lane = tid & 31;
  const int wid  = tid >> 5;
  const int wm   = wid & 3;    // warp grid 4(M) x 2(N)
  const int wn   = wid >> 2;
  const int grp  = lane >> 2;  // 0..7
  const int qp   = lane & 3;   // 0..3

  const int mt  = blockIdx.y;            // 0..1023 (m-tile over B*S)
  const int n0  = blockIdx.x * BN;       // x fastest => L2 reuse of A across n
  const size_t row0 = (size_t)mt * BM;
  const int bidx = mt >> 4;              // 16 m-tiles per batch row

  const __half* Ag = g_encH + row0 * KDIM;
  const __half* Bg = g_WhT + (size_t)n0 * KDIM;

  // ---- ldmatrix per-lane byte offsets (within one stage) ----
  const int l8 = lane & 7;
  const int lm = lane >> 3;
  uint32_t aOff[2];
  #pragma unroll
  for (int mf = 0; mf < 2; mf++) {
    const int row = wm * 32 + mf * 16 + l8 + (lm & 1) * 8;
    const int col = (lm >> 1) * 8;
    aOff[mf] = (uint32_t)((row * PADH + col) * 2);
  }
  uint32_t bOff[4];
  #pragma unroll
  for (int nfp = 0; nfp < 4; nfp++) {
    const int row = wn * 64 + nfp * 16 + l8 + (lm >> 1) * 8;
    const int col = (lm & 1) * 8;
    bOff[nfp] = (uint32_t)((row * PADH + col) * 2);
  }
  const uint32_t aB0 = smem_u32(&As[0][0][0]);
  const uint32_t bB0 = smem_u32(&Bs[0][0][0]);

  float acc[2][8][4];
  #pragma unroll
  for (int i = 0; i < 2; i++)
    #pragma unroll
    for (int j = 0; j < 8; j++)
      #pragma unroll
      for (int e = 0; e < 4; e++) acc[i][j][e] = 0.f;

  // stage in hWh/v while prologue loads fly
  const int KT = KDIM / BK;  // 64
  load_tile(As[0], Bs[0], Ag, Bg, 0 * BK, tid);
  load_tile(As[1], Bs[1], Ag, Bg, 1 * BK, tid);
  load_tile(As[2], Bs[2], Ag, Bg, 2 * BK, tid);
  if (tid < BN) {
    s_hwh[tid] = g_hWh[(size_t)bidx * NDIM + n0 + tid];
    s_v[tid]   = v[n0 + tid];
  }

  for (int kt = 0; kt < KT; kt++) {
    const int cur = kt & 3;
    if (kt < KT - 2)
      asm volatile("cp.async.wait_group 2;\n" ::: "memory");
    else if (kt == KT - 2)
      asm volatile("cp.async.wait_group 1;\n" ::: "memory");
    else
      asm volatile("cp.async.wait_group 0;\n" ::: "memory");
    __syncthreads();   // stage `cur` visible; stage (kt+3)%4 free (read in kt-1)

    const int ktn = kt + 3;                 // refill overlaps compute below
    if (ktn < KT) {
      const int sn = ktn & 3;
      load_tile(As[sn], Bs[sn], Ag, Bg, ktn * BK, tid);
    }

    const uint32_t aBase = aB0 + (uint32_t)cur * STAGE_B;
    const uint32_t bBase = bB0 + (uint32_t)cur * STAGE_B;
    #pragma unroll
    for (int ks = 0; ks < 2; ks++) {
      const uint32_t kByte = (uint32_t)(ks * 16 * 2);
      uint32_t a[2][4];
      #pragma unroll
      for (int mf = 0; mf < 2; mf++)
        ldsm4(a[mf][0], a[mf][1], a[mf][2], a[mf][3], aBase + aOff[mf] + kByte);
      uint32_t b[8][2];
      #pragma unroll
      for (int nfp = 0; nfp < 4; nfp++)
        ldsm4(b[nfp * 2][0], b[nfp * 2][1], b[nfp * 2 + 1][0], b[nfp * 2 + 1][1],
              bBase + bOff[nfp] + kByte);
      #pragma unroll
      for (int mf = 0; mf < 2; mf++)
        #pragma unroll
        for (int nf = 0; nf < 8; nf++)
          mma16(acc[mf][nf], a[mf], b[nf]);
    }
  }
  __syncthreads();

  // ---------------- epilogue: + hWh, tanh, dot v, reduce over this n-tile
  float p[2][2] = {{0.f, 0.f}, {0.f, 0.f}};
  #pragma unroll
  for (int mf = 0; mf < 2; mf++)
    #pragma unroll
    for (int nf = 0; nf < 8; nf++)
      #pragma unroll
      for (int e = 0; e < 4; e++) {
        // C frag: d0:(g,2t) d1:(g,2t+1) d2:(g+8,2t) d3:(g+8,2t+1)
        const int nl = wn * 64 + nf * 8 + qp * 2 + (e & 1);
        const float en = tanhf(acc[mf][nf][e] + s_hwh[nl]);
        p[mf][e >> 1] += en * s_v[nl];
      }
  #pragma unroll
  for (int mf = 0; mf < 2; mf++)
    #pragma unroll
    for (int h = 0; h < 2; h++) {
      float x = p[mf][h];
      x += __shfl_xor_sync(0xffffffffu, x, 1);
      x += __shfl_xor_sync(0xffffffffu, x, 2);
      if (qp == 0) s_red[wn * BM + wm * 32 + mf * 16 + h * 8 + grp] = x;
    }
  __syncthreads();
  if (tid < BM)
    g_part[(size_t)blockIdx.x * (BDIM * SDIM) + row0 + tid] =
        s_red[tid] + s_red[BM + tid];
}

// ------------------------------------------ kernel 3: mask + softmax(S)
__global__ void softmax_kernel(const int* __restrict__ mask,
                               float* __restrict__ out) {
  const int bq = blockIdx.x;
  const int tid = threadIdx.x;
  float loc[8];
  float mx = -1e30f;
  #pragma unroll
  for (int i = 0; i < 8; i++) {
    const long long idx = (long long)bq * SDIM + i * 256 + tid;
    float sc = 0.0f;
    #pragma unroll
    for (int j = 0; j < 8; j++) sc += g_part[(long long)j * (BDIM * SDIM) + idx];
    if (mask[idx] == 0) sc = -1e9f;
    loc[i] = sc;
    mx = fmaxf(mx, sc);
  }
  __shared__ float sm[8];
  #pragma unroll
  for (int o = 16; o > 0; o >>= 1) mx = fmaxf(mx, __shfl_xor_sync(~0u, mx, o));
  if ((tid & 31) == 0) sm[tid >> 5] = mx;
  __syncthreads();
  if (tid < 32) {
    float t = (tid < 8) ? sm[tid] : -1e30f;
    #pragma unroll
    for (int o = 4; o > 0; o >>= 1) t = fmaxf(t, __shfl_xor_sync(~0u, t, o));
    if (tid == 0) sm[0] = t;
  }
  __syncthreads();
  mx = sm[0];

  float sum = 0.0f;
  #pragma unroll
  for (int i = 0; i < 8; i++) { loc[i] = expf(loc[i] - mx); sum += loc[i]; }
  __shared__ float ss[8];
  #pragma unroll
  for (int o = 16; o > 0; o >>= 1) sum += __shfl_xor_sync(~0u, sum, o);
  if ((tid & 31) == 0) ss[tid >> 5] = sum;
  __syncthreads();
  if (tid < 32) {
    float t = (tid < 8) ? ss[tid] : 0.0f;
    #pragma unroll
    for (int o = 4; o > 0; o >>= 1) t += __shfl_xor_sync(~0u, t, o);
    if (tid == 0) ss[0] = t;
  }
  __syncthreads();
  const float inv = 1.0f / ss[0];
  #pragma unroll
  for (int i = 0; i < 8; i++)
    out[(long long)bq * SDIM + i * 256 + tid] = loc[i] * inv;
}

// ----------------------------------------------------------------- launch
extern "C" void kernel_launch(void* const* d_in, const int* in_sizes, int n_in,
                              void* d_out, int out_size) {
  const float* hidden = nullptr;
  const float* enc    = nullptr;
  const int*   mask   = nullptr;
  const float* W      = nullptr;
  const float* b_attn = nullptr;
  const float* v      = nullptr;

  for (int pass = 0; pass < 2; pass++) {      // elements, then bytes
    const long long mul = (pass == 0) ? 1LL : 4LL;
    hidden = enc = W = b_attn = v = nullptr; mask = nullptr;
    for (int i = 0; i < n_in; i++) {
      const long long sz = (long long)in_sizes[i];
      if      (sz == 65536LL * mul)     hidden = (const float*)d_in[i];
      else if (sz == 268435456LL * mul) enc    = (const float*)d_in[i];
      else if (sz == 131072LL * mul)    mask   = (const int*)  d_in[i];
      else if (sz == 3145728LL * mul)   W      = (const float*)d_in[i];
      else if (sz == 1024LL * mul) {
        if (!b_attn) b_attn = (const float*)d_in[i];
        else         v      = (const float*)d_in[i];
      }
    }
    if (hidden && enc && mask && W && b_attn && v) break;
  }
  if (!hidden || !enc || !mask || !W || !b_attn || !v) {
    hidden = (const float*)d_in[0];
    enc    = (const float*)d_in[1];
    mask   = (const int*)  d_in[2];
    W      = (const float*)d_in[3];
    b_attn = (const float*)d_in[4];
    v      = (const float*)d_in[5];
  }
  float* out = (float*)d_out;   // (B,S) float32

  const int smem_bytes = 2 * NST * STAGE_B + (2 * BN + 2 * BM) * 4;  // 84032
  static bool attr_set = false;
  if (!attr_set) {
    cudaFuncSetAttribute(energy_fp16_kernel,
                         cudaFuncAttributeMaxDynamicSharedMemorySize, smem_bytes);
    attr_set = true;
  }

  enc2h_kernel<<<8192, 256>>>((const float4*)enc);
  wt_kernel<<<dim3(32, 64), dim3(32, 8)>>>(W);
  hwh_kernel<<<dim3(4, BDIM), 256>>>(hidden, W, b_attn);
  energy_fp16_kernel<<<dim3(8, 1024), 256, smem_bytes>>>(v);
  softmax_kernel<<<BDIM, 256>>>(mask, out);
}